// round 15
// baseline (speedup 1.0000x reference)
#include <cuda_runtime.h>
#include <math.h>
#include <stdint.h>

#define NB   4
#define HW   4096
#define DH   128
#define NTOK 4096
#define QKV_U32 (NTOK * DH / 2)   // 262144 u32 (bf16x2) per batch

// fp8 fragment images (r7/r14 layouts, verified):
__device__ uint32_t g_Q[NB * QKV_U32];
__device__ uint32_t g_K[NB * QKV_U32];
__device__ uint32_t g_V[NB * QKV_U32];
// Plain bf16 token rows [b][n][128], written by proj, read by repack:
__device__ uint32_t g_Qp[NB * QKV_U32];
__device__ uint32_t g_Kp[NB * QKV_U32];
__device__ uint32_t g_Vp[NB * QKV_U32];
__device__ float    g_O[NB * NTOK * DH];

// log2(e)/sqrt(128): Q pre-scale so softmax runs in exp2 domain.
#define QSCALE (0.08838834764831845f * 1.4426950408889634f)

__device__ __forceinline__ uint32_t pack_bf16(float lo, float hi) {
    uint32_t r; asm("cvt.rn.bf16x2.f32 %0, %1, %2;" : "=r"(r) : "f"(hi), "f"(lo)); return r;
}
__device__ __forceinline__ float ex2f(float x) {
    float y; asm("ex2.approx.f32 %0, %1;" : "=f"(y) : "f"(x)); return y;
}
__device__ __forceinline__ uint32_t f2tf(float x) {
    uint32_t u; asm("cvt.rna.tf32.f32 %0, %1;" : "=r"(u) : "f"(x)); return u;
}
__device__ __forceinline__ uint32_t pack4_e4m3(float f0, float f1, float f2, float f3) {
    uint32_t r;
    asm("{\n\t.reg .b16 lo, hi;\n\t"
        "cvt.rn.satfinite.e4m3x2.f32 lo, %2, %1;\n\t"
        "cvt.rn.satfinite.e4m3x2.f32 hi, %4, %3;\n\t"
        "mov.b32 %0, {lo, hi};\n\t}"
        : "=r"(r) : "f"(f0), "f"(f1), "f"(f2), "f"(f3));
    return r;
}
__device__ __forceinline__ void bf2f(uint32_t a, float& lo, float& hi) {
    lo = __uint_as_float(a << 16);
    hi = __uint_as_float(a & 0xFFFF0000u);
}
__device__ __forceinline__ void mma_tf32(float* d,
    uint32_t a0, uint32_t a1, uint32_t a2, uint32_t a3, uint32_t b0, uint32_t b1)
{
    asm volatile(
        "mma.sync.aligned.m16n8k8.row.col.f32.tf32.tf32.f32 "
        "{%0,%1,%2,%3},{%4,%5,%6,%7},{%8,%9},{%0,%1,%2,%3};"
        : "+f"(d[0]), "+f"(d[1]), "+f"(d[2]), "+f"(d[3])
        : "r"(a0), "r"(a1), "r"(a2), "r"(a3), "r"(b0), "r"(b1));
}
__device__ __forceinline__ void mma_e4m3(float* d,
    uint32_t a0, uint32_t a1, uint32_t a2, uint32_t a3, uint32_t b0, uint32_t b1)
{
    asm volatile(
        "mma.sync.aligned.m16n8k32.row.col.f32.e4m3.e4m3.f32 "
        "{%0,%1,%2,%3},{%4,%5,%6,%7},{%8,%9},{%0,%1,%2,%3};"
        : "+f"(d[0]), "+f"(d[1]), "+f"(d[2]), "+f"(d[3])
        : "r"(a0), "r"(a1), "r"(a2), "r"(a3), "r"(b0), "r"(b1));
}
__device__ __forceinline__ void mma_e4m3_init(float* d,
    uint32_t a0, uint32_t a1, uint32_t a2, uint32_t a3, uint32_t b0, uint32_t b1)
{
    asm volatile(
        "mma.sync.aligned.m16n8k32.row.col.f32.e4m3.e4m3.f32 "
        "{%0,%1,%2,%3},{%4,%5,%6,%7},{%8,%9},{%10,%11,%12,%13};"
        : "=f"(d[0]), "=f"(d[1]), "=f"(d[2]), "=f"(d[3])
        : "r"(a0), "r"(a1), "r"(a2), "r"(a3), "r"(b0), "r"(b1),
          "f"(0.f), "f"(0.f), "f"(0.f), "f"(0.f));
}
__device__ __forceinline__ void cp_async16(void* smem_dst, const void* gmem_src) {
    uint32_t s = (uint32_t)__cvta_generic_to_shared(smem_dst);
    asm volatile("cp.async.cg.shared.global [%0], [%1], 16;\n" :: "r"(s), "l"(gmem_src));
}
#define CP_COMMIT() asm volatile("cp.async.commit_group;\n" ::: "memory")
template<int N> __device__ __forceinline__ void cp_wait() {
    asm volatile("cp.async.wait_group %0;\n" :: "n"(N) : "memory");
}

// ---------------------------------------------------------------------------
// tf32 QKV projection (r12 verbatim): coalesced plain bf16 token-row emit.
// ---------------------------------------------------------------------------
__global__ __launch_bounds__(256, 2) void proj_qkv_t(
    const float* __restrict__ xu, const float* __restrict__ xl,
    const float* __restrict__ wq, const float* __restrict__ bq,
    const float* __restrict__ wk, const float* __restrict__ bk,
    const float* __restrict__ wv, const float* __restrict__ bv,
    uint32_t* __restrict__ Qp, uint32_t* __restrict__ Kp,
    uint32_t* __restrict__ Vp)
{
    extern __shared__ uint32_t shm[];
    uint32_t* Wf  = shm;
    float*    Csm = (float*)shm;
    float*    Xs  = (float*)(shm + 16896);

    const int m = blockIdx.y % 3, b = blockIdx.y / 3;
    const int CIN = (m == 0) ? 64 : 128;
    const int KS  = CIN >> 3;
    const int NK  = CIN >> 4;
    const int CLOG = (m == 0) ? 6 : 7;
    const float* x    = (m == 0) ? xu + (size_t)b * 64 * HW
                                 : xl + (size_t)b * 128 * HW;
    const float* w    = (m == 0) ? wq : (m == 1) ? wk : wv;
    const float* bias = (m == 0) ? bq : (m == 1) ? bk : bv;

    const int s0  = blockIdx.x * 128;
    const int tid = threadIdx.x, wp = tid >> 5, lane = tid & 31;
    const int g = lane >> 2, tq = lane & 3;
    const int wm = wp >> 2, wn = wp & 3;

    auto issueX = [&](int j) {
        float* dst = Xs + (j & 3) * 2176;
#pragma unroll
        for (int tt = 0; tt < 2; tt++) {
            int f = tid + 256 * tt;
            int row = f >> 5, col = (f & 31) * 4;
            cp_async16(dst + row * 136 + col,
                       x + (size_t)(j * 16 + row) * HW + s0 + col);
        }
        CP_COMMIT();
    };
    issueX(0); issueX(1);
    if (NK > 2) issueX(2); else CP_COMMIT();

    for (int e = tid; e < (128 << CLOG); e += 256) {
        int mrow = e >> CLOG, k = e & (CIN - 1);
        int mt = mrow >> 4, r = mrow & 15, gg = r & 7, hi = r >> 3;
        int ks = k >> 3, kk = k & 7, c = kk & 3, ch = kk >> 2;
        Wf[((mt * KS + ks) * 32 + gg * 4 + c) * 4 + hi + 2 * ch] = f2tf(w[e]);
    }

    float acc[4][4][4];
#pragma unroll
    for (int i = 0; i < 4; i++)
#pragma unroll
        for (int j = 0; j < 4; j++)
#pragma unroll
            for (int k = 0; k < 4; k++) acc[i][j][k] = 0.f;

    __syncthreads();

    for (int j = 0; j < NK; j++) {
        cp_wait<2>();
        __syncthreads();
        if (j + 3 < NK) issueX(j + 3); else CP_COMMIT();
        const float* Xb = Xs + (j & 3) * 2176;

#pragma unroll
        for (int h = 0; h < 2; h++) {
            const int ks = j * 2 + h;
            uint4 a[4];
#pragma unroll
            for (int mtl = 0; mtl < 4; mtl++)
                a[mtl] = *(const uint4*)&Wf[(((wm * 4 + mtl) * KS + ks) * 32 + lane) * 4];
#pragma unroll
            for (int ntl = 0; ntl < 4; ntl++) {
                int nn = wn * 32 + ntl * 8 + g;
                uint32_t b0 = f2tf(Xb[(h * 8 + tq) * 136 + nn]);
                uint32_t b1 = f2tf(Xb[(h * 8 + tq + 4) * 136 + nn]);
#pragma unroll
                for (int mtl = 0; mtl < 4; mtl++)
                    mma_tf32(acc[mtl][ntl], a[mtl].x, a[mtl].y, a[mtl].z, a[mtl].w, b0, b1);
            }
        }
    }

    __syncthreads();
#pragma unroll
    for (int mtl = 0; mtl < 4; mtl++) {
        int row = wm * 64 + mtl * 16 + g;
#pragma unroll
        for (int ntl = 0; ntl < 4; ntl++) {
            int col = wn * 32 + ntl * 8 + 2 * tq;
            *(float2*)&Csm[row * 132 + col]       = make_float2(acc[mtl][ntl][0], acc[mtl][ntl][1]);
            *(float2*)&Csm[(row + 8) * 132 + col] = make_float2(acc[mtl][ntl][2], acc[mtl][ntl][3]);
        }
    }
    __syncthreads();

    uint32_t* P = (m == 0) ? Qp : (m == 1) ? Kp : Vp;
#pragma unroll
    for (int cc = 0; cc < 16; cc++) {
        const int c  = cc * 8 + wp;
        const int sl = lane * 4;
        float4 vv4 = *(const float4*)&Csm[c * 132 + sl];
        const float bv_ = bias[c];
        float v0 = vv4.x + bv_, v1 = vv4.y + bv_;
        float v2 = vv4.z + bv_, v3 = vv4.w + bv_;
        if (m == 0) { v0 *= QSCALE; v1 *= QSCALE; v2 *= QSCALE; v3 *= QSCALE; }
        const int n = c * 32 + blockIdx.x;
        uint2 val;
        val.x = pack_bf16(v0, v1);
        val.y = pack_bf16(v2, v3);
        *(uint2*)(P + ((size_t)(b * NTOK + n)) * 64 + lane * 2) = val;
    }
}

// ---------------------------------------------------------------------------
// Repack (r14 verbatim): plain bf16 rows -> fp8 fragment images.
// ---------------------------------------------------------------------------
__global__ __launch_bounds__(256) void repack_kernel(
    const uint32_t* __restrict__ Qp, const uint32_t* __restrict__ Kp,
    const uint16_t* __restrict__ Vp,
    uint32_t* __restrict__ Qi, uint32_t* __restrict__ Ki,
    uint32_t* __restrict__ Vi)
{
    const int tid = threadIdx.x, wp = tid >> 5, lane = tid & 31;
    const int kind = blockIdx.y, b = blockIdx.z;
    const int chunk = blockIdx.x * 8 + wp;     // [0, 1024)
    const int g = lane >> 2, t = lane & 3;

    uint32_t out[4];
    if (kind == 0) {
        const int mt = chunk >> 2, ks = chunk & 3;
        const uint32_t* P = Qp + (size_t)b * QKV_U32;
#pragma unroll
        for (int j = 0; j < 4; j++) {
            int hi = j & 1, h = j >> 1;
            int n = mt * 16 + 8 * hi + g;
            int du = ks * 16 + h * 8 + t * 2;
            uint2 a = *(const uint2*)(P + (size_t)n * 64 + du);
            float f0, f1, f2, f3;
            bf2f(a.x, f0, f1); bf2f(a.y, f2, f3);
            out[j] = pack4_e4m3(f0, f1, f2, f3);
        }
        *(uint4*)(Qi + ((size_t)b * 1024 + chunk) * 128 + lane * 4) = *(uint4*)out;
    } else if (kind == 1) {
        const int tile = chunk >> 4, ntp = (chunk >> 2) & 3, ks = chunk & 3;
        const uint32_t* P = Kp + (size_t)b * QKV_U32;
#pragma unroll
        for (int sub = 0; sub < 4; sub++) {
            int odd = sub >> 1, h = sub & 1;
            int n = tile * 64 + (ntp * 2 + odd) * 8 + g;
            int du = ks * 16 + h * 8 + t * 2;
            uint2 a = *(const uint2*)(P + (size_t)n * 64 + du);
            float f0, f1, f2, f3;
            bf2f(a.x, f0, f1); bf2f(a.y, f2, f3);
            out[sub] = pack4_e4m3(f0, f1, f2, f3);
        }
        *(uint4*)(Ki + (size_t)b * 131072 + (size_t)tile * 2048
                  + ((size_t)(ntp * 4 + ks) * 32 + lane) * 4) = *(uint4*)out;
    } else {
        const int tile = chunk >> 4, dtp = (chunk >> 1) & 7, u = chunk & 1;
        const uint16_t* P = Vp + (size_t)b * (QKV_U32 * 2);
#pragma unroll
        for (int sub = 0; sub < 4; sub++) {
            int odd = sub >> 1, hv = sub & 1;
            int d = dtp * 16 + odd * 8 + g;
            float f[4];
#pragma unroll
            for (int cv = 0; cv < 4; cv++) {
                int j = u * 32 + hv * 16 + (cv >> 1) * 8 + t * 2 + (cv & 1);
                uint32_t bits = P[(size_t)(tile * 64 + j) * 128 + d];
                f[cv] = __uint_as_float(bits << 16);
            }
            out[sub] = pack4_e4m3(f[0], f[1], f[2], f[3]);
        }
        *(uint4*)(Vi + (size_t)b * 131072 + (size_t)tile * 2048
                  + ((size_t)(dtp * 2 + u) * 32 + lane) * 4) = *(uint4*)out;
    }
}

// ---------------------------------------------------------------------------
// fp8 flash, 512 threads: BM=128, key-split warp pairs. Warp w (m-slice wm =
// w&7, key half kh = w>>3) handles keys [32kh, 32kh+32) of each 64-key tile.
// o/l partials merged once in epilogue via smem (no-max softmax is linear).
// 4 warps/SMSP -> sibling warps' MMAs cover each other's softmax latency.
// ---------------------------------------------------------------------------
__global__ __launch_bounds__(512, 1) void flash_kernel(
    const uint4* __restrict__ Qg, const char* __restrict__ Kg_,
    const char* __restrict__ Vg_, float* __restrict__ O)
{
    extern __shared__ uint32_t sm[];   // loop: 4 stages x (K 2048 u32 + V 2048 u32) = 64KB
                                       // epilogue: 64KB o-merge + 2KB l-merge (reused)
    const int b = blockIdx.y, bx = blockIdx.x;
    const int tid = threadIdx.x, w = tid >> 5, lane = tid & 31;
    const int g = lane >> 2, t = lane & 3;
    const int wm = w & 7, kh = w >> 3;

    const char* Kg = Kg_ + (size_t)b * 524288;
    const char* Vg = Vg_ + (size_t)b * 524288;

    auto issueKV = [&](int i) {
        uint32_t st = (uint32_t)(i & 3) * 4096;
        int f = tid * 16;   // 512 threads x 16B = 8KB tile in one shot
        cp_async16((char*)(sm + st) + f, Kg + (size_t)i * 8192 + f);
        cp_async16((char*)(sm + st + 2048) + f, Vg + (size_t)i * 8192 + f);
        CP_COMMIT();
    };
    issueKV(0); issueKV(1); issueKV(2);

    // Q A-frags (4 k32 chunks) for rows [wm*16, wm*16+16)
    uint4 q[4];
    {
        const uint4* qp = Qg + ((size_t)(b * 256 + bx * 8 + wm) * 4) * 32 + lane;
#pragma unroll
        for (int ks = 0; ks < 4; ks++) q[ks] = qp[ks * 32];
    }

    float o[16][4];
#pragma unroll
    for (int dt = 0; dt < 16; dt++)
#pragma unroll
        for (int j = 0; j < 4; j++) o[dt][j] = 0.f;
    float ls0 = 0.f, ls1 = 0.f;
    float sf[4][4];

    // S(0): this warp's 2 ntp groups (keys 32kh .. 32kh+31)
    cp_wait<2>();
    __syncthreads();
#pragma unroll
    for (int ks = 0; ks < 4; ks++) {
#pragma unroll
        for (int p = 0; p < 2; p++) {
            const int ntp = kh * 2 + p;
            uint4 kb = *(const uint4*)(sm + (ntp * 4 + ks) * 128 + lane * 4);
            if (ks == 0) {
                mma_e4m3_init(sf[p * 2],     q[ks].x, q[ks].y, q[ks].z, q[ks].w, kb.x, kb.y);
                mma_e4m3_init(sf[p * 2 + 1], q[ks].x, q[ks].y, q[ks].z, q[ks].w, kb.z, kb.w);
            } else {
                mma_e4m3(sf[p * 2],     q[ks].x, q[ks].y, q[ks].z, q[ks].w, kb.x, kb.y);
                mma_e4m3(sf[p * 2 + 1], q[ks].x, q[ks].y, q[ks].z, q[ks].w, kb.z, kb.w);
            }
        }
    }

    for (int i = 0; i < 64; i++) {
        cp_wait<1>();
        __syncthreads();
        if (i + 3 < 64) issueKV(i + 3); else CP_COMMIT();

        const uint32_t* ksb = sm + (uint32_t)((i + 1) & 3) * 4096;
        const uint32_t* vsb = sm + (uint32_t)(i & 3) * 4096 + 2048;

        // ---- softmax (no max, exp2) on this warp's 32 keys ----
        uint32_t pa[4];
        {
            float e[4][4];
#pragma unroll
            for (int k = 0; k < 4; k++) {
                e[k][0] = ex2f(sf[k][0]); e[k][1] = ex2f(sf[k][1]);
                e[k][2] = ex2f(sf[k][2]); e[k][3] = ex2f(sf[k][3]);
                ls0 += e[k][0] + e[k][1];
                ls1 += e[k][2] + e[k][3];
            }
            pa[0] = pack4_e4m3(e[0][0], e[0][1], e[1][0], e[1][1]);
            pa[1] = pack4_e4m3(e[0][2], e[0][3], e[1][2], e[1][3]);
            pa[2] = pack4_e4m3(e[2][0], e[2][1], e[3][0], e[3][1]);
            pa[3] = pack4_e4m3(e[2][2], e[2][3], e[3][2], e[3][3]);
        }

        // ---- S(i+1) ----
        if (i < 63) {
#pragma unroll
            for (int ks = 0; ks < 4; ks++) {
#pragma unroll
                for (int p = 0; p < 2; p++) {
                    const int ntp = kh * 2 + p;
                    uint4 kb = *(const uint4*)(ksb + (ntp * 4 + ks) * 128 + lane * 4);
                    if (ks == 0) {
                        mma_e4m3_init(sf[p * 2],     q[ks].x, q[ks].y, q[ks].z, q[ks].w, kb.x, kb.y);
                        mma_e4m3_init(sf[p * 2 + 1], q[ks].x, q[ks].y, q[ks].z, q[ks].w, kb.z, kb.w);
                    } else {
                        mma_e4m3(sf[p * 2],     q[ks].x, q[ks].y, q[ks].z, q[ks].w, kb.x, kb.y);
                        mma_e4m3(sf[p * 2 + 1], q[ks].x, q[ks].y, q[ks].z, q[ks].w, kb.z, kb.w);
                    }
                }
            }
        }

        // ---- PV(i): o += P @ V over this warp's key half (u = kh) ----
#pragma unroll
        for (int dtp = 0; dtp < 8; dtp++) {
            uint4 vv = *(const uint4*)(vsb + (dtp * 2 + kh) * 128 + lane * 4);
            mma_e4m3(o[dtp * 2],     pa[0], pa[1], pa[2], pa[3], vv.x, vv.y);
            mma_e4m3(o[dtp * 2 + 1], pa[0], pa[1], pa[2], pa[3], vv.z, vv.w);
        }
    }

    // ---- epilogue: merge warp pairs (kh=1 -> smem -> kh=0 adds), normalize ----
    __syncthreads();   // all KV smem reads done; safe to reuse
    float* mo = (float*)sm;            // 8 x 8KB o buffers
    float* ml = (float*)sm + 16384;    // 8 x 64 floats l buffers (at +64KB)

    if (kh == 1) {
        float* base = mo + wm * 2048;
#pragma unroll
        for (int dt = 0; dt < 16; dt++)
            *(float4*)(base + dt * 128 + lane * 4) =
                make_float4(o[dt][0], o[dt][1], o[dt][2], o[dt][3]);
        ml[wm * 64 + lane * 2]     = ls0;
        ml[wm * 64 + lane * 2 + 1] = ls1;
    }
    __syncthreads();
    if (kh == 0) {
        float* base = mo + wm * 2048;
#pragma unroll
        for (int dt = 0; dt < 16; dt++) {
            float4 v = *(const float4*)(base + dt * 128 + lane * 4);
            o[dt][0] += v.x; o[dt][1] += v.y; o[dt][2] += v.z; o[dt][3] += v.w;
        }
        ls0 += ml[wm * 64 + lane * 2];
        ls1 += ml[wm * 64 + lane * 2 + 1];

        ls0 += __shfl_xor_sync(0xffffffffu, ls0, 1);
        ls0 += __shfl_xor_sync(0xffffffffu, ls0, 2);
        ls1 += __shfl_xor_sync(0xffffffffu, ls1, 1);
        ls1 += __shfl_xor_sync(0xffffffffu, ls1, 2);
        const float inv0 = 1.0f / ls0, inv1 = 1.0f / ls1;

        float* Ob = O + ((size_t)(b * NTOK) + bx * 128 + wm * 16) * DH;
#pragma unroll
        for (int dt = 0; dt < 16; dt++) {
            *(float2*)(Ob + g * DH + dt * 8 + 2 * t) =
                make_float2(o[dt][0] * inv0, o[dt][1] * inv0);
            *(float2*)(Ob + (g + 8) * DH + dt * 8 + 2 * t) =
                make_float2(o[dt][2] * inv1, o[dt][3] * inv1);
        }
    }
}

// ---------------------------------------------------------------------------
// tf32 final conv (r13 verbatim): 64-cout tiles, 3 CTAs/SM.
// ---------------------------------------------------------------------------
__global__ __launch_bounds__(256, 3) void proj_out_t(
    const float* __restrict__ Oin, const float* __restrict__ w,
    const float* __restrict__ bias, const float* __restrict__ res,
    float* __restrict__ out)
{
    extern __shared__ uint32_t shm[];
    uint32_t* Wf = shm;                       // [mt4][16][lane32][4] tf32 (32KB)
    float*    Xs = (float*)(shm + 8192);      // 4 stages x [16][136] fp32

    const int b  = blockIdx.y;
    const int s0 = blockIdx.x * 128;
    const int crow0 = blockIdx.z * 64;
    const int tid = threadIdx.x, wp = tid >> 5, lane = tid & 31;
    const int g = lane >> 2, tq = lane & 3;
    const int wm = wp >> 2, wn = wp & 3;

    const float* x = Oin + (size_t)b * 128 * HW;

    auto issueX = [&](int j) {
        float* dst = Xs + (j & 3) * 2176;
#pragma unroll
        for (int tt = 0; tt < 2; tt++) {
            int f = tid + 256 * tt;
            int row = f >> 5, col = (f & 31) * 4;
            cp_async16(dst + row * 136 + col,
                       x + (size_t)(j * 16 + row) * HW + s0 + col);
        }
        CP_COMMIT();
    };
    issueX(0); issueX(1); issueX(2);

    for (int e = tid; e < 64 * 128; e += 256) {
        int mrow = e >> 7, k = e & 127;
        int mt = mrow >> 4, r = mrow & 15, gg = r & 7, hi = r >> 3;
        int ks = k >> 3, kk = k & 7, c = kk & 3, ch = kk >> 2;
        Wf[((mt * 16 + ks) * 32 + gg * 4 + c) * 4 + hi + 2 * ch] =
            f2tf(w[(size_t)(crow0 + mrow) * 128 + k]);
    }

    float acc[2][4][4];
#pragma unroll
    for (int i = 0; i < 2; i++)
#pragma unroll
        for (int j = 0; j < 4; j++)
#pragma unroll
            for (int k = 0; k < 4; k++) acc[i][j][k] = 0.f;

    __syncthreads();

    for (int j = 0; j < 8; j++) {
        cp_wait<2>();
        __syncthreads();
        if (j + 3 < 8) issueX(j + 3); else CP_COMMIT();
        const float* Xb = Xs + (j & 3) * 2176;

#pragma unroll
        for (int h = 0; h < 2; h++) {
            const int ks = j * 2 + h;
            uint4 a[2];
#pragma unroll
            for (int mtl = 0; mtl < 2; mtl++)
                a[mtl] = *(const uint4*)&Wf[(((wm * 2 + mtl) * 16 + ks) * 32 + lane) * 4];
#pragma unroll
            for (int ntl = 0; ntl < 4; ntl++) {
                int nn = wn * 32 + ntl * 8 + g;
                uint32_t b0 = f2tf(Xb[(h * 8 + tq) * 136 + nn]);
                uint32_t b1 = f2tf(Xb[(h * 8 + tq + 4) * 136 + nn]);
#pragma unroll
                for (int mtl = 0; mtl < 2; mtl++)
                    mma_tf32(acc[mtl][ntl], a[mtl].x, a[mtl].y, a[mtl].z, a[mtl].w, b0, b1);
            }
        }
    }

#pragma unroll
    for (int mtl = 0; mtl < 2; mtl++) {
        int row0 = crow0 + wm * 32 + mtl * 16 + g;
        float bv0 = bias[row0], bv1 = bias[row0 + 8];
#pragma unroll
        for (int ntl = 0; ntl < 4; ntl++) {
            int col = s0 + wn * 32 + ntl * 8 + 2 * tq;
            size_t i0 = ((size_t)b * 128 + row0) * HW + col;
            size_t i1 = ((size_t)b * 128 + row0 + 8) * HW + col;
            float2 r0 = *(const float2*)(res + i0);
            float2 r1 = *(const float2*)(res + i1);
            *(float2*)(out + i0) = make_float2(acc[mtl][ntl][0] + bv0 + r0.x,
                                               acc[mtl][ntl][1] + bv0 + r0.y);
            *(float2*)(out + i1) = make_float2(acc[mtl][ntl][2] + bv1 + r1.x,
                                               acc[mtl][ntl][3] + bv1 + r1.y);
        }
    }
}

static const int FLASH_SMEM = 65536 + 2048;          // 64KB KV / o-merge + 2KB l-merge
static const int QKV_SMEM   = 67584 + 34816;         // 102400 B
static const int POUT_SMEM  = 32768 + 34816;         // 67584 B

extern "C" void kernel_launch(void* const* d_in, const int* in_sizes, int n_in,
                              void* d_out, int out_size)
{
    const float* x_upper = (const float*)d_in[0];
    const float* x_lower = (const float*)d_in[1];
    const float* wq = (const float*)d_in[2];
    const float* bq = (const float*)d_in[3];
    const float* wk = (const float*)d_in[4];
    const float* bk = (const float*)d_in[5];
    const float* wv = (const float*)d_in[6];
    const float* bv = (const float*)d_in[7];
    const float* wo = (const float*)d_in[8];
    const float* bo = (const float*)d_in[9];
    float* out = (float*)d_out;

    uint32_t *Qi, *Ki, *Vi, *Qp, *Kp, *Vp; float* Op;
    cudaGetSymbolAddress((void**)&Qi, g_Q);
    cudaGetSymbolAddress((void**)&Ki, g_K);
    cudaGetSymbolAddress((void**)&Vi, g_V);
    cudaGetSymbolAddress((void**)&Qp, g_Qp);
    cudaGetSymbolAddress((void**)&Kp, g_Kp);
    cudaGetSymbolAddress((void**)&Vp, g_Vp);
    cudaGetSymbolAddress((void**)&Op, g_O);

    cudaFuncSetAttribute(flash_kernel,
                         cudaFuncAttributeMaxDynamicSharedMemorySize, FLASH_SMEM);
    cudaFuncSetAttribute(proj_qkv_t,
                         cudaFuncAttributeMaxDynamicSharedMemorySize, QKV_SMEM);
    cudaFuncSetAttribute(proj_out_t,
                         cudaFuncAttributeMaxDynamicSharedMemorySize, POUT_SMEM);

    proj_qkv_t<<<dim3(32, 12), 256, QKV_SMEM>>>(x_upper, x_lower,
                                                wq, bq, wk, bk, wv, bv,
                                                Qp, Kp, Vp);

    repack_kernel<<<dim3(128, 3, NB), 256>>>(Qp, Kp, (const uint16_t*)Vp,
                                             Qi, Ki, Vi);

    flash_kernel<<<dim3(NTOK / 128, NB), 512, FLASH_SMEM>>>(
        (const uint4*)Qi, (const char*)Ki, (const char*)Vi, Op);

    proj_out_t<<<dim3(32, 4, 2), 256, POUT_SMEM>>>(Op, wo, bo, x_lower, out);
}

// round 16
// speedup vs baseline: 1.1805x; 1.1805x over previous
#include <cuda_runtime.h>
#include <math.h>
#include <stdint.h>

#define NB   4
#define HW   4096
#define DH   128
#define NTOK 4096
#define QKV_U32 (NTOK * DH / 2)   // 262144 u32 (bf16x2) per batch

// bf16 fragment images (consumed by flash, r6 layouts):
__device__ uint32_t g_Q[NB * QKV_U32];
__device__ uint32_t g_K[NB * QKV_U32];
__device__ uint32_t g_V[NB * QKV_U32];
// Plain bf16 token rows [b][n][128], written by proj, read by repack:
__device__ uint32_t g_Qp[NB * QKV_U32];
__device__ uint32_t g_Kp[NB * QKV_U32];
__device__ uint32_t g_Vp[NB * QKV_U32];
__device__ float    g_O[NB * NTOK * DH];
// tf32 weight A-fragment images (built once by prep_w):
__device__ uint32_t g_Wq[8192];    // [mt8][ks8][lane32][4]
__device__ uint32_t g_Wk[16384];   // [mt8][ks16][lane32][4]
__device__ uint32_t g_Wv[16384];
__device__ uint32_t g_Wo[16384];

// log2(e)/sqrt(128): Q pre-scale so softmax runs in exp2 domain.
#define QSCALE (0.08838834764831845f * 1.4426950408889634f)

__device__ __forceinline__ uint32_t pack_bf16(float lo, float hi) {
    uint32_t r; asm("cvt.rn.bf16x2.f32 %0, %1, %2;" : "=r"(r) : "f"(hi), "f"(lo)); return r;
}
__device__ __forceinline__ float ex2f(float x) {
    float y; asm("ex2.approx.f32 %0, %1;" : "=f"(y) : "f"(x)); return y;
}
__device__ __forceinline__ uint32_t f2tf(float x) {
    uint32_t u; asm("cvt.rna.tf32.f32 %0, %1;" : "=r"(u) : "f"(x)); return u;
}
__device__ __forceinline__ void mma_tf32(float* d,
    uint32_t a0, uint32_t a1, uint32_t a2, uint32_t a3, uint32_t b0, uint32_t b1)
{
    asm volatile(
        "mma.sync.aligned.m16n8k8.row.col.f32.tf32.tf32.f32 "
        "{%0,%1,%2,%3},{%4,%5,%6,%7},{%8,%9},{%0,%1,%2,%3};"
        : "+f"(d[0]), "+f"(d[1]), "+f"(d[2]), "+f"(d[3])
        : "r"(a0), "r"(a1), "r"(a2), "r"(a3), "r"(b0), "r"(b1));
}
__device__ __forceinline__ void mma_bf16(float* d,
    uint32_t a0, uint32_t a1, uint32_t a2, uint32_t a3, uint32_t b0, uint32_t b1)
{
    asm volatile(
        "mma.sync.aligned.m16n8k16.row.col.f32.bf16.bf16.f32 "
        "{%0,%1,%2,%3},{%4,%5,%6,%7},{%8,%9},{%0,%1,%2,%3};"
        : "+f"(d[0]), "+f"(d[1]), "+f"(d[2]), "+f"(d[3])
        : "r"(a0), "r"(a1), "r"(a2), "r"(a3), "r"(b0), "r"(b1));
}
__device__ __forceinline__ void mma_bf16_init(float* d,
    uint32_t a0, uint32_t a1, uint32_t a2, uint32_t a3, uint32_t b0, uint32_t b1)
{
    asm volatile(
        "mma.sync.aligned.m16n8k16.row.col.f32.bf16.bf16.f32 "
        "{%0,%1,%2,%3},{%4,%5,%6,%7},{%8,%9},{%10,%11,%12,%13};"
        : "=f"(d[0]), "=f"(d[1]), "=f"(d[2]), "=f"(d[3])
        : "r"(a0), "r"(a1), "r"(a2), "r"(a3), "r"(b0), "r"(b1),
          "f"(0.f), "f"(0.f), "f"(0.f), "f"(0.f));
}
__device__ __forceinline__ void cp_async16(void* smem_dst, const void* gmem_src) {
    uint32_t s = (uint32_t)__cvta_generic_to_shared(smem_dst);
    asm volatile("cp.async.cg.shared.global [%0], [%1], 16;\n" :: "r"(s), "l"(gmem_src));
}
#define CP_COMMIT() asm volatile("cp.async.commit_group;\n" ::: "memory")
template<int N> __device__ __forceinline__ void cp_wait() {
    asm volatile("cp.async.wait_group %0;\n" :: "n"(N) : "memory");
}

// ---------------------------------------------------------------------------
// prep_w: build tf32 A-frag images for wq/wk/wv/wo once.
// blockIdx.y selects image. Thread = one (mt, ks, lane); writes uint4.
// Inverse map: gg=lane>>2, c=lane&3; j=hi+2ch -> row=mt*16+gg+8hi, k=ks*8+c+4ch.
// ---------------------------------------------------------------------------
__global__ __launch_bounds__(256) void prep_w(
    const float* __restrict__ wq, const float* __restrict__ wk,
    const float* __restrict__ wv, const float* __restrict__ wo,
    uint32_t* __restrict__ iq, uint32_t* __restrict__ ik,
    uint32_t* __restrict__ iv, uint32_t* __restrict__ io)
{
    const int img = blockIdx.y;
    const int CIN = (img == 0) ? 64 : 128;
    const int KS  = CIN >> 3;
    const int idx = blockIdx.x * 256 + threadIdx.x;   // (mt*KS + ks)*32 + lane
    if (idx >= 8 * KS * 32) return;
    const int lane = idx & 31, ksmt = idx >> 5;
    const int ks = ksmt % KS, mt = ksmt / KS;
    const int gg = lane >> 2, c = lane & 3;

    const float* w = (img == 0) ? wq : (img == 1) ? wk : (img == 2) ? wv : wo;
    uint32_t* out  = (img == 0) ? iq : (img == 1) ? ik : (img == 2) ? iv : io;

    uint32_t v[4];
#pragma unroll
    for (int j = 0; j < 4; j++) {
        int hi = j & 1, ch = j >> 1;
        int row = mt * 16 + gg + 8 * hi;
        int k   = ks * 8 + c + 4 * ch;
        v[j] = f2tf(w[(size_t)row * CIN + k]);
    }
    *(uint4*)(out + (size_t)idx * 4) = *(uint4*)v;
}

// ---------------------------------------------------------------------------
// tf32 QKV projection: W A-frags straight from gmem image (L2-hot LDG.128);
// X 4-stage cp.async; coalesced plain bf16 token-row emit (r12).
// ---------------------------------------------------------------------------
__global__ __launch_bounds__(256, 2) void proj_qkv_t(
    const float* __restrict__ xu, const float* __restrict__ xl,
    const uint32_t* __restrict__ iq, const uint32_t* __restrict__ ik,
    const uint32_t* __restrict__ iv,
    const float* __restrict__ bq, const float* __restrict__ bk,
    const float* __restrict__ bv,
    uint32_t* __restrict__ Qp, uint32_t* __restrict__ Kp,
    uint32_t* __restrict__ Vp)
{
    extern __shared__ uint32_t shm[];
    float* Csm = (float*)shm;                  // [128][132] fp32 (67584B)
    float* Xs  = (float*)(shm + 16896);        // 4 stages x [16][136] fp32

    const int m = blockIdx.y % 3, b = blockIdx.y / 3;
    const int CIN = (m == 0) ? 64 : 128;
    const int KS  = CIN >> 3;
    const int NK  = CIN >> 4;
    const float* x    = (m == 0) ? xu + (size_t)b * 64 * HW
                                 : xl + (size_t)b * 128 * HW;
    const uint32_t* Wimg = (m == 0) ? iq : (m == 1) ? ik : iv;
    const float* bias = (m == 0) ? bq : (m == 1) ? bk : bv;

    const int s0  = blockIdx.x * 128;
    const int tid = threadIdx.x, wp = tid >> 5, lane = tid & 31;
    const int g = lane >> 2, tq = lane & 3;
    const int wm = wp >> 2, wn = wp & 3;

    auto issueX = [&](int j) {
        float* dst = Xs + (j & 3) * 2176;
#pragma unroll
        for (int tt = 0; tt < 2; tt++) {
            int f = tid + 256 * tt;
            int row = f >> 5, col = (f & 31) * 4;
            cp_async16(dst + row * 136 + col,
                       x + (size_t)(j * 16 + row) * HW + s0 + col);
        }
        CP_COMMIT();
    };
    issueX(0); issueX(1);
    if (NK > 2) issueX(2); else CP_COMMIT();

    float acc[4][4][4];
#pragma unroll
    for (int i = 0; i < 4; i++)
#pragma unroll
        for (int j = 0; j < 4; j++)
#pragma unroll
            for (int k = 0; k < 4; k++) acc[i][j][k] = 0.f;

    for (int j = 0; j < NK; j++) {
        cp_wait<2>();
        __syncthreads();
        if (j + 3 < NK) issueX(j + 3); else CP_COMMIT();
        const float* Xb = Xs + (j & 3) * 2176;

#pragma unroll
        for (int h = 0; h < 2; h++) {
            const int ks = j * 2 + h;
            uint4 a[4];
#pragma unroll
            for (int mtl = 0; mtl < 4; mtl++)
                a[mtl] = *(const uint4*)(Wimg +
                    ((size_t)((wm * 4 + mtl) * KS + ks) * 32 + lane) * 4);
#pragma unroll
            for (int ntl = 0; ntl < 4; ntl++) {
                int nn = wn * 32 + ntl * 8 + g;
                uint32_t b0 = f2tf(Xb[(h * 8 + tq) * 136 + nn]);
                uint32_t b1 = f2tf(Xb[(h * 8 + tq + 4) * 136 + nn]);
#pragma unroll
                for (int mtl = 0; mtl < 4; mtl++)
                    mma_tf32(acc[mtl][ntl], a[mtl].x, a[mtl].y, a[mtl].z, a[mtl].w, b0, b1);
            }
        }
    }

    // C -> smem -> coalesced plain emit
    __syncthreads();
#pragma unroll
    for (int mtl = 0; mtl < 4; mtl++) {
        int row = wm * 64 + mtl * 16 + g;
#pragma unroll
        for (int ntl = 0; ntl < 4; ntl++) {
            int col = wn * 32 + ntl * 8 + 2 * tq;
            *(float2*)&Csm[row * 132 + col]       = make_float2(acc[mtl][ntl][0], acc[mtl][ntl][1]);
            *(float2*)&Csm[(row + 8) * 132 + col] = make_float2(acc[mtl][ntl][2], acc[mtl][ntl][3]);
        }
    }
    __syncthreads();

    uint32_t* P = (m == 0) ? Qp : (m == 1) ? Kp : Vp;
#pragma unroll
    for (int cc = 0; cc < 16; cc++) {
        const int c  = cc * 8 + wp;
        const int sl = lane * 4;
        float4 vv4 = *(const float4*)&Csm[c * 132 + sl];
        const float bv_ = bias[c];
        float v0 = vv4.x + bv_, v1 = vv4.y + bv_;
        float v2 = vv4.z + bv_, v3 = vv4.w + bv_;
        if (m == 0) { v0 *= QSCALE; v1 *= QSCALE; v2 *= QSCALE; v3 *= QSCALE; }
        const int n = c * 32 + blockIdx.x;
        uint2 val;
        val.x = pack_bf16(v0, v1);
        val.y = pack_bf16(v2, v3);
        *(uint2*)(P + ((size_t)(b * NTOK + n)) * 64 + lane * 2) = val;
    }
}

// ---------------------------------------------------------------------------
// Repack (r12 verbatim): plain bf16 rows -> bf16 fragment images.
// ---------------------------------------------------------------------------
__global__ __launch_bounds__(256) void repack_kernel(
    const uint32_t* __restrict__ Qp, const uint32_t* __restrict__ Kp,
    const uint16_t* __restrict__ Vp,
    uint32_t* __restrict__ Qi, uint32_t* __restrict__ Ki,
    uint32_t* __restrict__ Vi)
{
    const int tid = threadIdx.x, wp = tid >> 5, lane = tid & 31;
    const int kind = blockIdx.y, b = blockIdx.z;
    const int chunk = blockIdx.x * 8 + wp;
    const int big = chunk >> 3, ks = chunk & 7;
    const int g = lane >> 2, t = lane & 3;

    uint4 out;
    if (kind == 0) {
        const uint32_t* P = Qp + (size_t)b * QKV_U32;
        int r0 = (big * 16 + g) * 64 + ks * 8 + t;
        out.x = P[r0];
        out.y = P[r0 + 8 * 64];
        out.z = P[r0 + 4];
        out.w = P[r0 + 8 * 64 + 4];
        *(uint4*)(Qi + (((size_t)b * 256 + big) * 8 + ks) * 128 + lane * 4) = out;
    } else if (kind == 1) {
        const uint32_t* P = Kp + (size_t)b * QKV_U32;
        int r0 = (big * 16 + g) * 64 + ks * 8 + t;
        out.x = P[r0];
        out.y = P[r0 + 4];
        out.z = P[r0 + 8 * 64];
        out.w = P[r0 + 8 * 64 + 4];
        *(uint4*)(Ki + (((size_t)b * 256 + big) * 8 + ks) * 128 + lane * 4) = out;
    } else {
        const uint16_t* P = Vp + (size_t)b * (QKV_U32 * 2);
        uint32_t r[4];
#pragma unroll
        for (int sub = 0; sub < 4; sub++) {
            int odd = sub >> 1, j = sub & 1;
            int n0 = big * 16 + 8 * j + 2 * t;
            int d  = ks * 16 + 8 * odd + g;
            uint32_t lo = P[(size_t)n0 * 128 + d];
            uint32_t hi = P[(size_t)(n0 + 1) * 128 + d];
            r[sub] = lo | (hi << 16);
        }
        out.x = r[0]; out.y = r[1]; out.z = r[2]; out.w = r[3];
        *(uint4*)(Vi + (((size_t)b * 256 + big) * 8 + ks) * 128 + lane * 4) = out;
    }
}

// ---------------------------------------------------------------------------
// bf16 flash (r13 verbatim, best known: split-group pipelines, named barriers).
// ---------------------------------------------------------------------------
__global__ __launch_bounds__(256, 1) void flash_kernel(
    const uint4* __restrict__ Qg, const char* __restrict__ Kg_,
    const char* __restrict__ Vg_, float* __restrict__ O)
{
    extern __shared__ uint32_t sm[];   // group grp at sm + grp*24576: 3 stages x (K 4096 + V 4096)

    const int b = blockIdx.y, bx = blockIdx.x;
    const int tid = threadIdx.x, w = tid >> 5, lane = tid & 31;
    const int g = lane >> 2, t = lane & 3;
    const int grp = w >> 2;
    const int gtid = tid & 127;
    uint32_t* gb = sm + grp * 24576;

    const char* Kg = Kg_ + (size_t)b * (QKV_U32 * 4);
    const char* Vg = Vg_ + (size_t)b * (QKV_U32 * 4);

    auto barG = [&]() {
        asm volatile("bar.sync %0, %1;" :: "r"(grp + 1), "r"(128) : "memory");
    };

    auto issueKV = [&](int i) {
        uint32_t* st = gb + (i % 3) * 8192;
        const char* kg = Kg + (size_t)i * 16384;
        const char* vg = Vg + (size_t)i * 16384;
#pragma unroll
        for (int tt = 0; tt < 8; tt++) {
            int f = (gtid + 128 * tt) * 16;
            cp_async16((char*)st + f, kg + f);
        }
#pragma unroll
        for (int tt = 0; tt < 8; tt++) {
            int f = (gtid + 128 * tt) * 16;
            cp_async16((char*)(st + 4096) + f, vg + f);
        }
        CP_COMMIT();
    };
    issueKV(0); issueKV(1); issueKV(2);

    uint4 q[8];
    {
        const uint4* qp = Qg + ((size_t)(b * 256 + bx * 8 + w) * 8) * 32 + lane;
#pragma unroll
        for (int ks = 0; ks < 8; ks++) q[ks] = qp[ks * 32];
    }

    float o[16][4];
#pragma unroll
    for (int dt = 0; dt < 16; dt++)
#pragma unroll
        for (int j = 0; j < 4; j++) o[dt][j] = 0.f;
    float ls0 = 0.f, ls1 = 0.f;
    float sf[8][4];

    cp_wait<2>();
    barG();
    {
        const uint32_t* ksb = gb;
#pragma unroll
        for (int ks = 0; ks < 8; ks++) {
#pragma unroll
            for (int ntp = 0; ntp < 4; ntp++) {
                uint4 kb = *(const uint4*)(ksb + (ntp * 8 + ks) * 128 + lane * 4);
                if (ks == 0) {
                    mma_bf16_init(sf[ntp * 2],     q[ks].x, q[ks].y, q[ks].z, q[ks].w, kb.x, kb.y);
                    mma_bf16_init(sf[ntp * 2 + 1], q[ks].x, q[ks].y, q[ks].z, q[ks].w, kb.z, kb.w);
                } else {
                    mma_bf16(sf[ntp * 2],     q[ks].x, q[ks].y, q[ks].z, q[ks].w, kb.x, kb.y);
                    mma_bf16(sf[ntp * 2 + 1], q[ks].x, q[ks].y, q[ks].z, q[ks].w, kb.z, kb.w);
                }
            }
        }
    }

    for (int i = 0; i < 64; i++) {
        cp_wait<1>();
        barG();

        const uint32_t* ksb = gb + ((i + 1) % 3) * 8192;
        const uint32_t* vsb = gb + (i % 3) * 8192 + 4096;

        uint32_t p[16];
#pragma unroll
        for (int u = 0; u < 4; u++) {
            float a0 = ex2f(sf[2*u][0]),   a1 = ex2f(sf[2*u][1]);
            float a2 = ex2f(sf[2*u][2]),   a3 = ex2f(sf[2*u][3]);
            float b0 = ex2f(sf[2*u+1][0]), b1 = ex2f(sf[2*u+1][1]);
            float b2 = ex2f(sf[2*u+1][2]), b3 = ex2f(sf[2*u+1][3]);
            ls0 += a0 + a1 + b0 + b1;
            ls1 += a2 + a3 + b2 + b3;
            p[u*4+0] = pack_bf16(a0, a1);
            p[u*4+1] = pack_bf16(a2, a3);
            p[u*4+2] = pack_bf16(b0, b1);
            p[u*4+3] = pack_bf16(b2, b3);
        }

        if (i < 63) {
#pragma unroll
            for (int ks = 0; ks < 8; ks++) {
#pragma unroll
                for (int ntp = 0; ntp < 4; ntp++) {
                    uint4 kb = *(const uint4*)(ksb + (ntp * 8 + ks) * 128 + lane * 4);
                    if (ks == 0) {
                        mma_bf16_init(sf[ntp * 2],     q[ks].x, q[ks].y, q[ks].z, q[ks].w, kb.x, kb.y);
                        mma_bf16_init(sf[ntp * 2 + 1], q[ks].x, q[ks].y, q[ks].z, q[ks].w, kb.z, kb.w);
                    } else {
                        mma_bf16(sf[ntp * 2],     q[ks].x, q[ks].y, q[ks].z, q[ks].w, kb.x, kb.y);
                        mma_bf16(sf[ntp * 2 + 1], q[ks].x, q[ks].y, q[ks].z, q[ks].w, kb.z, kb.w);
                    }
                }
            }
        }

#pragma unroll
        for (int u = 0; u < 4; u++) {
#pragma unroll
            for (int dtp = 0; dtp < 8; dtp++) {
                uint4 vv = *(const uint4*)(vsb + (u * 8 + dtp) * 128 + lane * 4);
                mma_bf16(o[dtp * 2],     p[u*4+0], p[u*4+1], p[u*4+2], p[u*4+3], vv.x, vv.y);
                mma_bf16(o[dtp * 2 + 1], p[u*4+0], p[u*4+1], p[u*4+2], p[u*4+3], vv.z, vv.w);
            }
        }

        barG();
        if (i + 3 < 64) issueKV(i + 3);
        else            CP_COMMIT();
    }

    ls0 += __shfl_xor_sync(0xffffffffu, ls0, 1);
    ls0 += __shfl_xor_sync(0xffffffffu, ls0, 2);
    ls1 += __shfl_xor_sync(0xffffffffu, ls1, 1);
    ls1 += __shfl_xor_sync(0xffffffffu, ls1, 2);
    const float inv0 = 1.0f / ls0, inv1 = 1.0f / ls1;

    float* Ob = O + ((size_t)(b * NTOK) + bx * 128 + w * 16) * DH;
#pragma unroll
    for (int dt = 0; dt < 16; dt++) {
        *(float2*)(Ob + g * DH + dt * 8 + 2 * t) =
            make_float2(o[dt][0] * inv0, o[dt][1] * inv0);
        *(float2*)(Ob + (g + 8) * DH + dt * 8 + 2 * t) =
            make_float2(o[dt][2] * inv1, o[dt][3] * inv1);
    }
}

// ---------------------------------------------------------------------------
// tf32 final conv: wo A-frags from gmem image; smem = X pipeline only
// (34.8 KB -> 4+ CTAs/SM). 64-cout tiles. out = wo @ O + bo + x_lower.
// ---------------------------------------------------------------------------
__global__ __launch_bounds__(256, 4) void proj_out_t(
    const float* __restrict__ Oin, const uint32_t* __restrict__ io,
    const float* __restrict__ bias, const float* __restrict__ res,
    float* __restrict__ out)
{
    extern __shared__ uint32_t shm[];
    float* Xs = (float*)shm;                  // 4 stages x [16][136] fp32

    const int b  = blockIdx.y;
    const int s0 = blockIdx.x * 128;
    const int crow0 = blockIdx.z * 64;
    const int tid = threadIdx.x, wp = tid >> 5, lane = tid & 31;
    const int g = lane >> 2, tq = lane & 3;
    const int wm = wp >> 2, wn = wp & 3;

    const float* x = Oin + (size_t)b * 128 * HW;
    const uint32_t* Wimg = io + (size_t)(crow0 >> 4) * 16 * 128;  // mt offset

    auto issueX = [&](int j) {
        float* dst = Xs + (j & 3) * 2176;
#pragma unroll
        for (int tt = 0; tt < 2; tt++) {
            int f = tid + 256 * tt;
            int row = f >> 5, col = (f & 31) * 4;
            cp_async16(dst + row * 136 + col,
                       x + (size_t)(j * 16 + row) * HW + s0 + col);
        }
        CP_COMMIT();
    };
    issueX(0); issueX(1); issueX(2);

    float acc[2][4][4];
#pragma unroll
    for (int i = 0; i < 2; i++)
#pragma unroll
        for (int j = 0; j < 4; j++)
#pragma unroll
            for (int k = 0; k < 4; k++) acc[i][j][k] = 0.f;

    for (int j = 0; j < 8; j++) {
        cp_wait<2>();
        __syncthreads();
        if (j + 3 < 8) issueX(j + 3); else CP_COMMIT();
        const float* Xb = Xs + (j & 3) * 2176;

#pragma unroll
        for (int h = 0; h < 2; h++) {
            const int ks = j * 2 + h;
            uint4 a[2];
#pragma unroll
            for (int mtl = 0; mtl < 2; mtl++)
                a[mtl] = *(const uint4*)(Wimg +
                    ((size_t)((wm * 2 + mtl) * 16 + ks) * 32 + lane) * 4);
#pragma unroll
            for (int ntl = 0; ntl < 4; ntl++) {
                int nn = wn * 32 + ntl * 8 + g;
                uint32_t b0 = f2tf(Xb[(h * 8 + tq) * 136 + nn]);
                uint32_t b1 = f2tf(Xb[(h * 8 + tq + 4) * 136 + nn]);
#pragma unroll
                for (int mtl = 0; mtl < 2; mtl++)
                    mma_tf32(acc[mtl][ntl], a[mtl].x, a[mtl].y, a[mtl].z, a[mtl].w, b0, b1);
            }
        }
    }

#pragma unroll
    for (int mtl = 0; mtl < 2; mtl++) {
        int row0 = crow0 + wm * 32 + mtl * 16 + g;
        float bv0 = bias[row0], bv1 = bias[row0 + 8];
#pragma unroll
        for (int ntl = 0; ntl < 4; ntl++) {
            int col = s0 + wn * 32 + ntl * 8 + 2 * tq;
            size_t i0 = ((size_t)b * 128 + row0) * HW + col;
            size_t i1 = ((size_t)b * 128 + row0 + 8) * HW + col;
            float2 r0 = *(const float2*)(res + i0);
            float2 r1 = *(const float2*)(res + i1);
            *(float2*)(out + i0) = make_float2(acc[mtl][ntl][0] + bv0 + r0.x,
                                               acc[mtl][ntl][1] + bv0 + r0.y);
            *(float2*)(out + i1) = make_float2(acc[mtl][ntl][2] + bv1 + r1.x,
                                               acc[mtl][ntl][3] + bv1 + r1.y);
        }
    }
}

static const int FLASH_SMEM = 2 * 3 * 8192 * 4;      // 192 KB
static const int QKV_SMEM   = 67584 + 34816;         // 102400 B
static const int POUT_SMEM  = 34816;                 // X pipeline only

extern "C" void kernel_launch(void* const* d_in, const int* in_sizes, int n_in,
                              void* d_out, int out_size)
{
    const float* x_upper = (const float*)d_in[0];
    const float* x_lower = (const float*)d_in[1];
    const float* wq = (const float*)d_in[2];
    const float* bq = (const float*)d_in[3];
    const float* wk = (const float*)d_in[4];
    const float* bk = (const float*)d_in[5];
    const float* wv = (const float*)d_in[6];
    const float* bv = (const float*)d_in[7];
    const float* wo = (const float*)d_in[8];
    const float* bo = (const float*)d_in[9];
    float* out = (float*)d_out;

    uint32_t *Qi, *Ki, *Vi, *Qp, *Kp, *Vp, *Iq, *Ik, *Iv, *Io; float* Op;
    cudaGetSymbolAddress((void**)&Qi, g_Q);
    cudaGetSymbolAddress((void**)&Ki, g_K);
    cudaGetSymbolAddress((void**)&Vi, g_V);
    cudaGetSymbolAddress((void**)&Qp, g_Qp);
    cudaGetSymbolAddress((void**)&Kp, g_Kp);
    cudaGetSymbolAddress((void**)&Vp, g_Vp);
    cudaGetSymbolAddress((void**)&Op, g_O);
    cudaGetSymbolAddress((void**)&Iq, g_Wq);
    cudaGetSymbolAddress((void**)&Ik, g_Wk);
    cudaGetSymbolAddress((void**)&Iv, g_Wv);
    cudaGetSymbolAddress((void**)&Io, g_Wo);

    cudaFuncSetAttribute(flash_kernel,
                         cudaFuncAttributeMaxDynamicSharedMemorySize, FLASH_SMEM);
    cudaFuncSetAttribute(proj_qkv_t,
                         cudaFuncAttributeMaxDynamicSharedMemorySize, QKV_SMEM);
    cudaFuncSetAttribute(proj_out_t,
                         cudaFuncAttributeMaxDynamicSharedMemorySize, POUT_SMEM);

    prep_w<<<dim3(16, 4), 256>>>(wq, wk, wv, wo, Iq, Ik, Iv, Io);

    proj_qkv_t<<<dim3(32, 12), 256, QKV_SMEM>>>(x_upper, x_lower,
                                                Iq, Ik, Iv, bq, bk, bv,
                                                Qp, Kp, Vp);

    repack_kernel<<<dim3(256, 3, NB), 256>>>(Qp, Kp, (const uint16_t*)Vp,
                                             Qi, Ki, Vi);

    flash_kernel<<<dim3(NTOK / 128, NB), 256, FLASH_SMEM>>>(
        (const uint4*)Qi, (const char*)Ki, (const char*)Vi, Op);

    proj_out_t<<<dim3(32, 4, 2), 256, POUT_SMEM>>>(Op, Io, bo, x_lower, out);
}